// round 15
// baseline (speedup 1.0000x reference)
#include <cuda_runtime.h>

// GroCo loss v8 — fp8(e4m3) m16n8k32 Gram.
// R14 cycle accounting: legacy mma.sync on sm_103 is instruction-rate
// limited (~29 cyc/SMSP per mma regardless of schedule). Lever: double the
// MACs per instruction via e4m3 m16n8k32 (fragments = byte-doubled clones
// of the verified bf16 m16n8k16 layout; same ldmatrix addressing, chunk =
// 16 fp8). Rows scaled x8 before quantization (avoids e4m3 subnormals);
// sims recovered as dot/64. pos_sims exact fp32. zero+normalize+pos fused
// into one kernel (3 launches total).

#define BN 8192
#define DD 128
#define NTJ 64

__device__ unsigned g_q[2][BN * DD / 4];   // fp8 rows, 128B each
__device__ float    g_pos[BN];
__device__ double   g_acc;

// ---------------- helpers ----------------
__device__ __forceinline__ unsigned s2u(const void* p) {
    unsigned a;
    asm("{ .reg .u64 t; cvta.to.shared.u64 t, %1; cvt.u32.u64 %0, t; }"
        : "=r"(a) : "l"(p));
    return a;
}

// swizzled SMEM address for (row, 16B chunk) of a 128x128 fp8 tile:
// row stride 128B (8 chunks), chunk XORed with row&7 -> ldmatrix conflict-free.
__device__ __forceinline__ unsigned sw8(unsigned base, int row, int chunk) {
    return base + (unsigned)(row << 7) + (unsigned)(((chunk ^ (row & 7)) << 4));
}

// cp.async one 128x128 fp8 tile (row-major, 128B rows) into swizzled SMEM.
__device__ __forceinline__ void cpasync_tile8(unsigned sb,
                                              const char* src, int tid) {
#pragma unroll
    for (int i = 0; i < 4; ++i) {            // 1024 chunks / 256 threads
        int c = tid + (i << 8);
        int row = c >> 3, chunk = c & 7;
        unsigned dst = sw8(sb, row, chunk);
        asm volatile("cp.async.cg.shared.global [%0], [%1], 16;"
                     :: "r"(dst), "l"(src + c * 16) : "memory");
    }
}

// Branchless insert into ascending top-10 (t[0] = smallest kept).
__device__ __forceinline__ void topk_insert10(float (&t)[10], float v) {
#pragma unroll
    for (int k = 0; k < 9; ++k) t[k] = fminf(fmaxf(v, t[k]), t[k + 1]);
    t[9] = fmaxf(v, t[9]);
}

// per-row finalize: scale sims by 1/64, soft odd-even sort + BCE term sum.
__device__ __forceinline__ float row_loss(const float (&tt)[10], float pos) {
    float s[11];
#pragma unroll
    for (int k = 0; k < 10; ++k) s[k] = tt[k] * 0.015625f;
    s[10] = pos;

    const float INV_PI = 0.3183098861837907f;
    float alpha[55];
#pragma unroll
    for (int layer = 0; layer < 11; ++layer) {
        int off = layer & 1;
#pragma unroll
        for (int pi = 0; pi < 5; ++pi) {
            int ia = off + 2 * pi, ib = ia + 1;
            float av = s[ia], bv = s[ib];
            float al = atanf(bv - av) * INV_PI + 0.5f;
            alpha[layer * 5 + pi] = al;
            s[ia] = al * av + (1.0f - al) * bv;
            s[ib] = (1.0f - al) * av + al * bv;
        }
    }
    float wp[11], wn[11];
#pragma unroll
    for (int k = 0; k < 11; ++k) { wp[k] = 0.0f; wn[k] = 1.0f; }
    wp[10] = 1.0f; wn[10] = 0.0f;
#pragma unroll
    for (int layer = 10; layer >= 0; --layer) {
        int off = layer & 1;
#pragma unroll
        for (int pi = 0; pi < 5; ++pi) {
            int ia = off + 2 * pi, ib = ia + 1;
            float al = alpha[layer * 5 + pi];
            float pa = wp[ia], pb = wp[ib];
            wp[ia] = al * pa + (1.0f - al) * pb;
            wp[ib] = (1.0f - al) * pa + al * pb;
            float na = wn[ia], nb2 = wn[ib];
            wn[ia] = al * na + (1.0f - al) * nb2;
            wn[ib] = (1.0f - al) * na + al * nb2;
        }
    }
    float local = 0.0f;
#pragma unroll
    for (int i = 0; i < 11; ++i) {
        float ppos = fminf(fmaxf(wp[i], 0.0f), 1.0f);
        float pneg = fminf(fmaxf(wn[i], 0.0f), 1.0f);
        float tp = (i == 10) ? fmaxf(logf(ppos),        -100.0f)
                             : fmaxf(logf(1.0f - ppos), -100.0f);
        float tn = (i < 10)  ? fmaxf(logf(pneg),        -100.0f)
                             : fmaxf(logf(1.0f - pneg), -100.0f);
        local += tp + tn;
    }
    return local;
}

// ---------------- kernels ----------------
// Fused: g_acc zero + both-direction normalize->fp8(x8) + pos_sims.
__global__ void normalize_fused(const float* __restrict__ a1,
                                const float* __restrict__ a2) {
    if (blockIdx.x == 0 && threadIdx.x == 0) g_acc = 0.0;
    int gw   = (blockIdx.x * blockDim.x + threadIdx.x) >> 5;  // warp per row
    int lane = threadIdx.x & 31;
    if (gw >= BN) return;
    float4 va = reinterpret_cast<const float4*>(a1)[gw * (DD / 4) + lane];
    float4 vb = reinterpret_cast<const float4*>(a2)[gw * (DD / 4) + lane];
    float sa = va.x * va.x + va.y * va.y + va.z * va.z + va.w * va.w;
    float sb = vb.x * vb.x + vb.y * vb.y + vb.z * vb.z + vb.w * vb.w;
    float sab = va.x * vb.x + va.y * vb.y + va.z * vb.z + va.w * vb.w;
#pragma unroll
    for (int o = 16; o > 0; o >>= 1) {
        sa  += __shfl_xor_sync(0xffffffffu, sa, o);
        sb  += __shfl_xor_sync(0xffffffffu, sb, o);
        sab += __shfl_xor_sync(0xffffffffu, sab, o);
    }
    float ia = 1.0f / fmaxf(sqrtf(sa), 1e-8f);
    float ib = 1.0f / fmaxf(sqrtf(sb), 1e-8f);
    if (lane == 0) g_pos[gw] = sab * ia * ib;

    float fa = ia * 8.0f, fb = ib * 8.0f;
    unsigned short l16, h16;
    unsigned w;
    // dir 0
    asm("cvt.rn.satfinite.e4m3x2.f32 %0, %1, %2;" : "=h"(l16)
        : "f"(va.y * fa), "f"(va.x * fa));
    asm("cvt.rn.satfinite.e4m3x2.f32 %0, %1, %2;" : "=h"(h16)
        : "f"(va.w * fa), "f"(va.z * fa));
    w = (unsigned)l16 | ((unsigned)h16 << 16);
    g_q[0][gw * 32 + lane] = w;
    // dir 1
    asm("cvt.rn.satfinite.e4m3x2.f32 %0, %1, %2;" : "=h"(l16)
        : "f"(vb.y * fb), "f"(vb.x * fb));
    asm("cvt.rn.satfinite.e4m3x2.f32 %0, %1, %2;" : "=h"(h16)
        : "f"(vb.w * fb), "f"(vb.z * fb));
    w = (unsigned)l16 | ((unsigned)h16 << 16);
    g_q[1][gw * 32 + lane] = w;
}

// SMEM: A @0 (16KB), B0 @16384, B1 @32768, sred @49152 (2KB)
#define SMEM_DYN (49152 + 2048)

__global__ void __launch_bounds__(256, 1) gram_kernel() {
    extern __shared__ char smem[];
    unsigned sbase = s2u(smem);
    double* sred = (double*)(smem + 49152);
    int tid = threadIdx.x, w = tid >> 5, l = tid & 31;
    int dir = blockIdx.x >> 6, it = blockIdx.x & 63;
    const char* nb = (const char*)g_q[dir];

    // prologue: A tile + B tile 0
    cpasync_tile8(sbase, nb + (size_t)it * 128 * DD, tid);
    cpasync_tile8(sbase + 16384, nb, tid);
    asm volatile("cp.async.commit_group;" ::: "memory");
    asm volatile("cp.async.wait_group 0;" ::: "memory");
    __syncthreads();

    // A fragments: 4 k32-atoms, resident. m16n8k32 A-frag via ldmatrix.x4
    // (identical lane mapping to the verified bf16 path, chunk = 16 fp8):
    // g0..g3 -> (m+0,k_lo),(m+8,k_lo),(m+0,k_hi),(m+8,k_hi)
    unsigned af[4][4];
    {
        int g = l >> 3, ri = l & 7;
        int arow = w * 16 + ((g & 1) << 3) + ri;
        int cadd = g >> 1;
#pragma unroll
        for (int ka = 0; ka < 4; ++ka) {
            unsigned ad = sw8(sbase, arow, ka * 2 + cadd);
            asm volatile(
                "ldmatrix.sync.aligned.m8n8.x4.shared.b16 {%0,%1,%2,%3}, [%4];"
                : "=r"(af[ka][0]), "=r"(af[ka][1]), "=r"(af[ka][2]), "=r"(af[ka][3])
                : "r"(ad));
        }
    }

    float t0[10], t1[10];
#pragma unroll
    for (int k = 0; k < 10; ++k) { t0[k] = -1e30f; t1[k] = -1e30f; }
    int r0 = it * 128 + w * 16 + (l >> 2);
    int r1 = r0 + 8;
    int brow = l & 7;         // b-frag row-in-atom
    int bchunk = l >> 3;      // 0..3 within the 4-chunk (k=64) window
    int cbase = (l & 3) << 1; // col offset within n-atom for c-frag

#pragma unroll 1
    for (int jt = 0; jt < NTJ; ++jt) {
        unsigned bs = sbase + 16384 + (unsigned)((jt & 1) << 14);
        if (jt + 1 < NTJ) {  // prefetch next B into the other buffer
            cpasync_tile8(sbase + 16384 + (unsigned)(((jt + 1) & 1) << 14),
                          nb + (size_t)(jt + 1) * 128 * DD, tid);
            asm volatile("cp.async.commit_group;" ::: "memory");
        }

        float acc[16][4];
#pragma unroll
        for (int p = 0; p < 2; ++p) {   // two k=64 windows
#pragma unroll
            for (int n = 0; n < 16; ++n) {
                unsigned b0, b1, b2, b3;
                unsigned bd = sw8(bs, (n << 3) + brow, (p << 2) + bchunk);
                asm volatile(
                    "ldmatrix.sync.aligned.m8n8.x4.shared.b16 {%0,%1,%2,%3}, [%4];"
                    : "=r"(b0), "=r"(b1), "=r"(b2), "=r"(b3) : "r"(bd));
                if (p == 0) {
                    asm volatile(
                        "mma.sync.aligned.m16n8k32.row.col.f32.e4m3.e4m3.f32 "
                        "{%0,%1,%2,%3}, {%4,%5,%6,%7}, {%8,%9}, {%10,%10,%10,%10};"
                        : "=f"(acc[n][0]), "=f"(acc[n][1]),
                          "=f"(acc[n][2]), "=f"(acc[n][3])
                        : "r"(af[0][0]), "r"(af[0][1]), "r"(af[0][2]), "r"(af[0][3]),
                          "r"(b0), "r"(b1), "f"(0.0f));
                } else {
                    asm volatile(
                        "mma.sync.aligned.m16n8k32.row.col.f32.e4m3.e4m3.f32 "
                        "{%0,%1,%2,%3}, {%4,%5,%6,%7}, {%8,%9}, {%0,%1,%2,%3};"
                        : "+f"(acc[n][0]), "+f"(acc[n][1]),
                          "+f"(acc[n][2]), "+f"(acc[n][3])
                        : "r"(af[2 * p][0]), "r"(af[2 * p][1]),
                          "r"(af[2 * p][2]), "r"(af[2 * p][3]),
                          "r"(b0), "r"(b1));
                }
                asm volatile(
                    "mma.sync.aligned.m16n8k32.row.col.f32.e4m3.e4m3.f32 "
                    "{%0,%1,%2,%3}, {%4,%5,%6,%7}, {%8,%9}, {%0,%1,%2,%3};"
                    : "+f"(acc[n][0]), "+f"(acc[n][1]),
                      "+f"(acc[n][2]), "+f"(acc[n][3])
                    : "r"(af[2 * p + 1][0]), "r"(af[2 * p + 1][1]),
                      "r"(af[2 * p + 1][2]), "r"(af[2 * p + 1][3]),
                      "r"(b2), "r"(b3));
            }
        }

        // fold this tile's (64x-scaled) sims into per-lane top-10
        int jb = jt * 128 + cbase;
#pragma unroll
        for (int n = 0; n < 16; ++n) {
            int j0 = jb + (n << 3), j1 = j0 + 1;
            float v;
            v = acc[n][0]; if (v > t0[0] && j0 != r0) topk_insert10(t0, v);
            v = acc[n][1]; if (v > t0[0] && j1 != r0) topk_insert10(t0, v);
            v = acc[n][2]; if (v > t1[0] && j0 != r1) topk_insert10(t1, v);
            v = acc[n][3]; if (v > t1[0] && j1 != r1) topk_insert10(t1, v);
        }

        if (jt + 1 < NTJ)
            asm volatile("cp.async.wait_group 0;" ::: "memory");
        __syncthreads();
    }

    // quad butterfly merge (lanes 4q..4q+3 share rows); snapshot per step.
#pragma unroll
    for (int step = 1; step <= 2; step <<= 1) {
        float s0[10], s1[10];
#pragma unroll
        for (int k = 0; k < 10; ++k) { s0[k] = t0[k]; s1[k] = t1[k]; }
#pragma unroll
        for (int k = 0; k < 10; ++k) {
            float v0 = __shfl_xor_sync(0xffffffffu, s0[k], step);
            float v1 = __shfl_xor_sync(0xffffffffu, s1[k], step);
            if (v0 > t0[0]) topk_insert10(t0, v0);
            if (v1 > t1[0]) topk_insert10(t1, v1);
        }
    }

    float local = 0.0f;
    if ((l & 3) == 0) {
        local  = row_loss(t0, g_pos[r0]);
        local += row_loss(t1, g_pos[r1]);
    }
    sred[tid] = (double)local;
    __syncthreads();
#pragma unroll
    for (int st = 128; st > 0; st >>= 1) {
        if (tid < st) sred[tid] += sred[tid + st];
        __syncthreads();
    }
    if (tid == 0) atomicAdd(&g_acc, sred[0]);
}

__global__ void writeout_kernel(float* __restrict__ out) {
    out[0] = (float)(-g_acc / (4.0 * 11.0 * (double)BN));
}

extern "C" void kernel_launch(void* const* d_in, const int* in_sizes, int n_in,
                              void* d_out, int out_size) {
    const float* aug1 = (const float*)d_in[0];
    const float* aug2 = (const float*)d_in[1];
    float* out = (float*)d_out;

    cudaFuncSetAttribute(gram_kernel,
                         cudaFuncAttributeMaxDynamicSharedMemorySize, SMEM_DYN);

    normalize_fused<<<(BN * 32) / 256, 256>>>(aug1, aug2);
    gram_kernel<<<128, 256, SMEM_DYN>>>();
    writeout_kernel<<<1, 1>>>(out);
}